// round 16
// baseline (speedup 1.0000x reference)
#include <cuda_runtime.h>

// out[b,i,j,c1,c2,k]: k=0 -> x[b,i,c1,c2], k=1 -> x[b,j,c1,c2]
// B=64, GS=96, C=8. Tile (b,i,j) = 128 floats, interleaved (xi[e], xj[e]).
//
// R6 config (one CTA per (b,i), 32 regs, 8 CTA/SM, MLP=6 loads, 6x
// st.global.cs.v8.f32) with one change: j = warp*12 + it*2 + half, so each
// warp's 6 back-to-back stores cover a 6 KB CONTIGUOUS span (was 8 KB-strided)
// -> max DRAM row-buffer locality on the write stream. Each store instruction
// still writes 1024 B contiguous per warp; CTA covers all 96 j's once.

static constexpr int GS = 96;
static constexpr int ROW = 64;  // 8*8 floats per (b,g) block

__global__ void __launch_bounds__(256)
combo_kernel(const float* __restrict__ x, float* __restrict__ out)
{
    const int bi = blockIdx.x;            // b*GS + i
    const int t = threadIdx.x;
    const int lane16 = t & 15;            // element-group within half-warp
    const int half   = (t >> 4) & 1;      // which 16-lane group of the warp
    const int w      = t >> 5;            // warp id, 0..7
    const int jw     = w * 12 + half;     // warp's base j (+ it*2)

    // xi: this thread's 4 elements of x[b,i], loop-invariant
    const float4 a = *reinterpret_cast<const float4*>(x + bi * ROW + lane16 * 4);

    const float* xb = x + (bi / GS) * GS * ROW + lane16 * 4;   // x[b,0]+off
    float* outb = out + (size_t)bi * GS * 128 + lane16 * 8;    // out[b,i,0]+off

    // Preload all 6 xj vectors (independent loads, MLP=6; input L2-resident)
    float4 c[6];
#pragma unroll
    for (int it = 0; it < 6; ++it) {
        const int j = jw + it * 2;
        c[it] = *reinterpret_cast<const float4*>(xb + j * ROW);
    }

    // 6 back-to-back 256-bit streaming stores, 6 KB contiguous per warp
#pragma unroll
    for (int it = 0; it < 6; ++it) {
        const int j = jw + it * 2;
        float* p = outb + j * 128;
        asm volatile(
            "st.global.cs.v8.f32 [%0], {%1,%2,%3,%4,%5,%6,%7,%8};" ::
            "l"(p),
            "f"(a.x), "f"(c[it].x), "f"(a.y), "f"(c[it].y),
            "f"(a.z), "f"(c[it].z), "f"(a.w), "f"(c[it].w)
            : "memory");
    }
}

extern "C" void kernel_launch(void* const* d_in, const int* in_sizes, int n_in,
                              void* d_out, int out_size)
{
    const float* x = (const float*)d_in[0];
    float* out = (float*)d_out;

    // one block per (b, i): 64*96 = 6144 blocks
    combo_kernel<<<64 * GS, 256>>>(x, out);
}